// round 3
// baseline (speedup 1.0000x reference)
#include <cuda_runtime.h>
#include <cuda_bf16.h>
#include <cstdint>

// ---------------- problem constants ----------------
constexpr int B    = 2;
constexpr int N    = 6400;
constexpr int E    = 256;
constexpr int CAMS = 6;
constexpr int LVLS = 4;
constexpr int BN_PTS = B * N;          // 12800
__device__ constexpr int HGT[LVLS]  = {64, 32, 16, 8};
__device__ constexpr int WID[LVLS]  = {176, 88, 44, 22};
__device__ constexpr int LOFF[LVLS] = {0, 11264, 14080, 14784};
constexpr int TOTHW = 14960;           // sum of H*W

// ---------------- device scratch (no runtime alloc allowed) ----------------
__device__ float g_featT[(size_t)B * CAMS * TOTHW * E];   // ~184 MB, [b,c,hw,E]
__device__ float g_attn[BN_PTS * CAMS * LVLS];            // softmaxed weights
__device__ float g_uv[BN_PTS * CAMS * 2];                 // pixel coords
__device__ float g_agg[(size_t)BN_PTS * E];               // aggregation result
__device__ float g_tmp[(size_t)BN_PTS * E];               // after vp GEMM

// ---------------- 1) feature transpose: [b,c,E,H,W] -> [b,c,HW,E] ----------
__global__ __launch_bounds__(256) void transpose_kernel(
                                 const float* __restrict__ f0,
                                 const float* __restrict__ f1,
                                 const float* __restrict__ f2,
                                 const float* __restrict__ f3) {
    int z  = blockIdx.z;          // bc*4 + lvl
    int l  = z & 3;
    int bc = z >> 2;
    int HW = HGT[l] * WID[l];
    int hw0 = blockIdx.x * 32;
    if (hw0 >= HW) return;
    int e0  = blockIdx.y * 32;

    const float* src = (l == 0 ? f0 : l == 1 ? f1 : l == 2 ? f2 : f3)
                       + (size_t)bc * E * HW;
    float* dst = g_featT + ((size_t)bc * TOTHW + LOFF[l]) * E;

    __shared__ float tile[32][33];
    int tx = threadIdx.x, ty = threadIdx.y;   // (32,8)
    #pragma unroll
    for (int i = 0; i < 4; i++) {
        int e  = e0 + ty + i * 8;
        int hw = hw0 + tx;
        tile[ty + i * 8][tx] = (hw < HW) ? src[(size_t)e * HW + hw] : 0.0f;
    }
    __syncthreads();
    #pragma unroll
    for (int i = 0; i < 4; i++) {
        int hw = hw0 + ty + i * 8;
        int e  = e0 + tx;
        if (hw < HW) dst[(size_t)hw * E + e] = tile[tx][ty + i * 8];
    }
}

// ---------------- 2) prep: attn softmax + uv projection --------------------
// one warp per point
__global__ __launch_bounds__(256) void prep_kernel(
                            const float* __restrict__ instf,
                            const float* __restrict__ anchor,
                            const float* __restrict__ proj,
                            const float* __restrict__ attn_w,
                            const float* __restrict__ attn_b) {
    int warp = (blockIdx.x * blockDim.x + threadIdx.x) >> 5;
    int lane = threadIdx.x & 31;
    if (warp >= BN_PTS) return;
    int p = warp;
    int b = p / N;

    // ---- attention logits: 24 dots of length 256 ----
    const float* ifp = instf + (size_t)p * E;
    float v[8];
    #pragma unroll
    for (int k = 0; k < 8; k++) v[k] = ifp[k * 32 + lane];

    float logit[24];
    #pragma unroll
    for (int cl = 0; cl < 24; cl++) {
        const float* w = attn_w + cl * E;
        float s = 0.f;
        #pragma unroll
        for (int k = 0; k < 8; k++) s = fmaf(v[k], w[k * 32 + lane], s);
        #pragma unroll
        for (int o = 16; o; o >>= 1) s += __shfl_xor_sync(0xffffffffu, s, o);
        logit[cl] = s + attn_b[cl];
    }

    // ---- per-cam softmax over 4 levels; lane 0 stores ----
    if (lane == 0) {
        #pragma unroll
        for (int c = 0; c < CAMS; c++) {
            float l0 = logit[c * 4 + 0], l1 = logit[c * 4 + 1];
            float l2 = logit[c * 4 + 2], l3 = logit[c * 4 + 3];
            float mx = fmaxf(fmaxf(l0, l1), fmaxf(l2, l3));
            float e0 = expf(l0 - mx), e1 = expf(l1 - mx);
            float e2 = expf(l2 - mx), e3 = expf(l3 - mx);
            float inv = 1.0f / (e0 + e1 + e2 + e3);
            float* ap = g_attn + (size_t)p * 24 + c * 4;
            ap[0] = e0 * inv; ap[1] = e1 * inv; ap[2] = e2 * inv; ap[3] = e3 * inv;
        }
    }

    // ---- projection: lanes 0..5 handle one camera each ----
    float ax = anchor[(size_t)p * 11 + 0];
    float ay = anchor[(size_t)p * 11 + 1];
    float az = anchor[(size_t)p * 11 + 2];
    float sx = 1.0f / (1.0f + expf(-ax));
    float sy = 1.0f / (1.0f + expf(-ay));
    float sz = 1.0f / (1.0f + expf(-az));
    float X = sx * 102.4f - 51.2f;
    float Y = sy * 102.4f - 51.2f;
    float Z = sz * 8.0f   - 5.0f;

    if (lane < CAMS) {
        const float* P = proj + ((size_t)b * CAMS + lane) * 16;
        float c0 = P[0]  * X + P[1]  * Y + P[2]  * Z + P[3];
        float c1 = P[4]  * X + P[5]  * Y + P[6]  * Z + P[7];
        float c2 = P[8]  * X + P[9]  * Y + P[10] * Z + P[11];
        float d  = fmaxf(c2, 0.0001f);
        g_uv[(size_t)p * 12 + lane * 2 + 0] = c0 / d;
        g_uv[(size_t)p * 12 + lane * 2 + 1] = c1 / d;
    }
}

// ---------------- 3) bilinear gather + weighted aggregation ---------------
// one block per point; thread = channel e. Branches are uniform per block.
__global__ __launch_bounds__(256) void aggregate_kernel() {
    int p = blockIdx.x;
    int e = threadIdx.x;
    int b = p / N;

    __shared__ float s_attn[24];
    __shared__ float s_uv[12];
    if (e < 24) s_attn[e] = g_attn[(size_t)p * 24 + e];
    if (e < 12) s_uv[e]   = g_uv[(size_t)p * 12 + e];
    __syncthreads();

    float acc = 0.f;
    #pragma unroll
    for (int c = 0; c < CAMS; c++) {
        float x = s_uv[c * 2 + 0];
        float y = s_uv[c * 2 + 1];
        float x0 = floorf(x), y0 = floorf(y);
        float wx1 = x - x0, wx0 = 1.0f - wx1;
        float wy1 = y - y0, wy0 = 1.0f - wy1;
        const float* base = g_featT + ((size_t)b * CAMS + c) * TOTHW * E;
        #pragma unroll
        for (int l = 0; l < LVLS; l++) {
            const int Wl = WID[l], Hl = HGT[l], off = LOFF[l];
            float wa = s_attn[c * 4 + l];
            // 4 corners; uniform-bounds-checked, skip invalid
            #pragma unroll
            for (int cy = 0; cy < 2; cy++) {
                float yf = y0 + cy;
                float wy = cy ? wy1 : wy0;
                if (yf < 0.f || yf > (float)(Hl - 1)) continue;
                #pragma unroll
                for (int cx = 0; cx < 2; cx++) {
                    float xf = x0 + cx;
                    float wx = cx ? wx1 : wx0;
                    if (xf < 0.f || xf > (float)(Wl - 1)) continue;
                    float wgt = wa * wx * wy;
                    int xi = (int)xf, yi = (int)yf;
                    const float* fp = base + ((size_t)(off + yi * Wl + xi)) * E;
                    acc = fmaf(wgt, fp[e], acc);
                }
            }
        }
    }
    g_agg[(size_t)p * E + e] = acc;
}

// ---------------- 4) fused NT-GEMM:  C = (A [+Aadd]) @ W^T + bias ----------
// A: [M,256] row-major, W: [256,256] row-major, C: [M,256]
// mode 0: A=g_agg  -> C=g_tmp       (vp)
// mode 1: A=g_tmp +instf -> C=out   (op)
constexpr int GBM = 64, GBN = 64, GBK = 16;
__global__ __launch_bounds__(256) void gemm_nt_kernel(int mode,
                               const float* __restrict__ Wm,
                               const float* __restrict__ bias,
                               const float* __restrict__ Aadd,
                               float* __restrict__ Cout) {
    const int K = 256;
    const float* A = (mode == 0) ? g_agg : g_tmp;
    float* C       = (mode == 0) ? g_tmp : Cout;

    __shared__ float sA[GBK][GBM + 1];
    __shared__ float sB[GBK][GBN + 1];

    int bm = blockIdx.x * GBM;
    int bn = blockIdx.y * GBN;
    int t  = threadIdx.x;              // 256 threads
    int tx = t & 15, ty = t >> 4;

    float acc[4][4] = {};

    for (int k0 = 0; k0 < K; k0 += GBK) {
        #pragma unroll
        for (int i = 0; i < 4; i++) {
            int idx = t + i * 256;     // [0,1024)
            int m = idx >> 4;          // 0..63
            int k = idx & 15;
            float a = A[(size_t)(bm + m) * K + k0 + k];
            if (mode == 1) a += Aadd[(size_t)(bm + m) * K + k0 + k];
            sA[k][m] = a;
            sB[k][m] = Wm[(size_t)(bn + m) * K + k0 + k];
        }
        __syncthreads();
        #pragma unroll
        for (int k = 0; k < GBK; k++) {
            float ra[4], rb[4];
            #pragma unroll
            for (int i = 0; i < 4; i++) ra[i] = sA[k][ty * 4 + i];
            #pragma unroll
            for (int j = 0; j < 4; j++) rb[j] = sB[k][tx * 4 + j];
            #pragma unroll
            for (int i = 0; i < 4; i++)
                #pragma unroll
                for (int j = 0; j < 4; j++)
                    acc[i][j] = fmaf(ra[i], rb[j], acc[i][j]);
        }
        __syncthreads();
    }

    #pragma unroll
    for (int i = 0; i < 4; i++) {
        #pragma unroll
        for (int j = 0; j < 4; j++) {
            C[(size_t)(bm + ty * 4 + i) * 256 + bn + tx * 4 + j] =
                acc[i][j] + bias[bn + tx * 4 + j];
        }
    }
}

// ---------------- launch ----------------
extern "C" void kernel_launch(void* const* d_in, const int* in_sizes, int n_in,
                              void* d_out, int out_size) {
    const float* instf  = (const float*)d_in[0];
    const float* anchor = (const float*)d_in[1];
    const float* proj   = (const float*)d_in[2];
    const float* f0     = (const float*)d_in[3];
    const float* f1     = (const float*)d_in[4];
    const float* f2     = (const float*)d_in[5];
    const float* f3     = (const float*)d_in[6];
    const float* attn_w = (const float*)d_in[7];
    const float* attn_b = (const float*)d_in[8];
    const float* vp_w   = (const float*)d_in[9];
    const float* vp_b   = (const float*)d_in[10];
    const float* op_w   = (const float*)d_in[11];
    const float* op_b   = (const float*)d_in[12];
    float* out = (float*)d_out;

    // 1) transpose features to channel-last
    transpose_kernel<<<dim3(352, 8, B * CAMS * LVLS), dim3(32, 8)>>>(f0, f1, f2, f3);

    // 2) attn softmax + uv
    prep_kernel<<<(BN_PTS * 32 + 255) / 256, 256>>>(instf, anchor, proj, attn_w, attn_b);

    // 3) aggregate
    aggregate_kernel<<<BN_PTS, E>>>();

    // 4) GEMMs
    dim3 gg(BN_PTS / GBM, 256 / GBN);
    gemm_nt_kernel<<<gg, 256>>>(0, vp_w, vp_b, nullptr, out);
    gemm_nt_kernel<<<gg, 256>>>(1, op_w, op_b, instf, out);
}

// round 4
// speedup vs baseline: 1.5686x; 1.5686x over previous
#include <cuda_runtime.h>
#include <cuda_bf16.h>
#include <cstdint>

// ---------------- problem constants ----------------
constexpr int B    = 2;
constexpr int N    = 6400;
constexpr int E    = 256;
constexpr int CAMS = 6;
constexpr int LVLS = 4;
constexpr int BN_PTS = B * N;          // 12800
__device__ constexpr int HGT[LVLS]  = {64, 32, 16, 8};
__device__ constexpr int WID[LVLS]  = {176, 88, 44, 22};
__device__ constexpr int LOFF[LVLS] = {0, 11264, 14080, 14784};
constexpr int TOTHW = 14960;           // sum of H*W

// ---------------- device scratch (no runtime alloc allowed) ----------------
__device__ float g_featT[(size_t)B * CAMS * TOTHW * E];   // ~184 MB, [b,c,hw,E]
__device__ float g_attn[BN_PTS * CAMS * LVLS];            // softmaxed weights
__device__ float g_uv[BN_PTS * CAMS * 2];                 // pixel coords
__device__ float g_agg[(size_t)BN_PTS * E];               // aggregation result
__device__ float g_tmp[(size_t)BN_PTS * E];               // after vp GEMM

// ---------------- 1) feature transpose: [b,c,E,H,W] -> [b,c,HW,E] ----------
// one launch per level (template L) with an exact grid — no wasted blocks.
template <int L>
__global__ __launch_bounds__(256) void transpose_kernel(const float* __restrict__ src0) {
    constexpr int H  = (L == 0 ? 64 : L == 1 ? 32 : L == 2 ? 16 : 8);
    constexpr int W  = (L == 0 ? 176 : L == 1 ? 88 : L == 2 ? 44 : 22);
    constexpr int HW = H * W;
    constexpr int OFF = (L == 0 ? 0 : L == 1 ? 11264 : L == 2 ? 14080 : 14784);

    int bc  = blockIdx.z;                 // 0..11
    int hw0 = blockIdx.x * 32;
    int e0  = blockIdx.y * 32;

    const float* src = src0 + (size_t)bc * E * HW;
    float* dst = g_featT + ((size_t)bc * TOTHW + OFF) * E;

    __shared__ float tile[32][33];
    int tx = threadIdx.x, ty = threadIdx.y;   // (32,8)
    #pragma unroll
    for (int i = 0; i < 4; i++) {
        int e  = e0 + ty + i * 8;
        int hw = hw0 + tx;
        tile[ty + i * 8][tx] = (hw < HW) ? src[(size_t)e * HW + hw] : 0.0f;
    }
    __syncthreads();
    #pragma unroll
    for (int i = 0; i < 4; i++) {
        int hw = hw0 + ty + i * 8;
        int e  = e0 + tx;
        if (hw < HW) dst[(size_t)hw * E + e] = tile[tx][ty + i * 8];
    }
}

// ---------------- 2) prep: attn softmax + uv projection --------------------
// one warp per point
__global__ __launch_bounds__(256) void prep_kernel(
                            const float* __restrict__ instf,
                            const float* __restrict__ anchor,
                            const float* __restrict__ proj,
                            const float* __restrict__ attn_w,
                            const float* __restrict__ attn_b) {
    int warp = (blockIdx.x * blockDim.x + threadIdx.x) >> 5;
    int lane = threadIdx.x & 31;
    if (warp >= BN_PTS) return;
    int p = warp;
    int b = p / N;

    const float* ifp = instf + (size_t)p * E;
    float v[8];
    #pragma unroll
    for (int k = 0; k < 8; k++) v[k] = ifp[k * 32 + lane];

    float logit[24];
    #pragma unroll
    for (int cl = 0; cl < 24; cl++) {
        const float* w = attn_w + cl * E;
        float s = 0.f;
        #pragma unroll
        for (int k = 0; k < 8; k++) s = fmaf(v[k], w[k * 32 + lane], s);
        #pragma unroll
        for (int o = 16; o; o >>= 1) s += __shfl_xor_sync(0xffffffffu, s, o);
        logit[cl] = s + attn_b[cl];
    }

    if (lane == 0) {
        #pragma unroll
        for (int c = 0; c < CAMS; c++) {
            float l0 = logit[c * 4 + 0], l1 = logit[c * 4 + 1];
            float l2 = logit[c * 4 + 2], l3 = logit[c * 4 + 3];
            float mx = fmaxf(fmaxf(l0, l1), fmaxf(l2, l3));
            float e0 = expf(l0 - mx), e1 = expf(l1 - mx);
            float e2 = expf(l2 - mx), e3 = expf(l3 - mx);
            float inv = 1.0f / (e0 + e1 + e2 + e3);
            float* ap = g_attn + (size_t)p * 24 + c * 4;
            ap[0] = e0 * inv; ap[1] = e1 * inv; ap[2] = e2 * inv; ap[3] = e3 * inv;
        }
    }

    float ax = anchor[(size_t)p * 11 + 0];
    float ay = anchor[(size_t)p * 11 + 1];
    float az = anchor[(size_t)p * 11 + 2];
    float sx = 1.0f / (1.0f + expf(-ax));
    float sy = 1.0f / (1.0f + expf(-ay));
    float sz = 1.0f / (1.0f + expf(-az));
    float X = sx * 102.4f - 51.2f;
    float Y = sy * 102.4f - 51.2f;
    float Z = sz * 8.0f   - 5.0f;

    if (lane < CAMS) {
        const float* P = proj + ((size_t)b * CAMS + lane) * 16;
        float c0 = P[0]  * X + P[1]  * Y + P[2]  * Z + P[3];
        float c1 = P[4]  * X + P[5]  * Y + P[6]  * Z + P[7];
        float c2 = P[8]  * X + P[9]  * Y + P[10] * Z + P[11];
        float d  = fmaxf(c2, 0.0001f);
        g_uv[(size_t)p * 12 + lane * 2 + 0] = c0 / d;
        g_uv[(size_t)p * 12 + lane * 2 + 1] = c1 / d;
    }
}

// ---------------- 3) bilinear gather + weighted aggregation ---------------
// 4 points per block; 64 threads per point; each thread owns 4 channels (float4).
__global__ __launch_bounds__(256) void aggregate_kernel() {
    int t  = threadIdx.x;
    int pt = t >> 6;                 // 0..3  point-within-block
    int c4 = t & 63;                 // channel group (4 floats)
    int p  = blockIdx.x * 4 + pt;
    int b  = p / N;

    __shared__ float s_attn[4][24];
    __shared__ float s_uv[4][12];
    if (c4 < 24) s_attn[pt][c4] = g_attn[(size_t)p * 24 + c4];
    if (c4 < 12) s_uv[pt][c4]   = g_uv[(size_t)p * 12 + c4];
    __syncthreads();

    float4 acc = make_float4(0.f, 0.f, 0.f, 0.f);
    #pragma unroll
    for (int c = 0; c < CAMS; c++) {
        float x = s_uv[pt][c * 2 + 0];
        float y = s_uv[pt][c * 2 + 1];
        float x0 = floorf(x), y0 = floorf(y);
        float wx1 = x - x0, wx0 = 1.0f - wx1;
        float wy1 = y - y0, wy0 = 1.0f - wy1;
        const float* base = g_featT + ((size_t)b * CAMS + c) * TOTHW * E;
        #pragma unroll
        for (int l = 0; l < LVLS; l++) {
            const int Wl = WID[l], Hl = HGT[l], off = LOFF[l];
            float wa = s_attn[pt][c * 4 + l];
            #pragma unroll
            for (int cy = 0; cy < 2; cy++) {
                float yf = y0 + cy;
                float wy = cy ? wy1 : wy0;
                if (yf < 0.f || yf > (float)(Hl - 1)) continue;
                #pragma unroll
                for (int cx = 0; cx < 2; cx++) {
                    float xf = x0 + cx;
                    float wx = cx ? wx1 : wx0;
                    if (xf < 0.f || xf > (float)(Wl - 1)) continue;
                    float wgt = wa * wx * wy;
                    int xi = (int)xf, yi = (int)yf;
                    const float4* fp = (const float4*)(base + ((size_t)(off + yi * Wl + xi)) * E) + c4;
                    float4 f = *fp;
                    acc.x = fmaf(wgt, f.x, acc.x);
                    acc.y = fmaf(wgt, f.y, acc.y);
                    acc.z = fmaf(wgt, f.z, acc.z);
                    acc.w = fmaf(wgt, f.w, acc.w);
                }
            }
        }
    }
    ((float4*)(g_agg + (size_t)p * E))[c4] = acc;
}

// ---------------- 4) fused NT-GEMM:  C = (A [+Aadd]) @ W^T + bias ----------
// A: [M,256] row-major, W: [256,256] row-major, C: [M,256]
// BM=128, BN=64, BK=16, 256 threads, microtile 8x4 (rows split 4+4).
constexpr int GBM = 128, GBN = 64, GBK = 16;
__global__ __launch_bounds__(256) void gemm_nt_kernel(int mode,
                               const float* __restrict__ Wm,
                               const float* __restrict__ bias,
                               const float* __restrict__ Aadd,
                               float* __restrict__ Cout) {
    const int K = 256;
    const float* A = (mode == 0) ? g_agg : g_tmp;
    float* C       = (mode == 0) ? g_tmp : Cout;

    __shared__ float sA[2][GBK][GBM + 4];
    __shared__ float sB[2][GBK][GBN + 4];

    int bm = blockIdx.x * GBM;
    int bn = blockIdx.y * GBN;
    int t  = threadIdx.x;              // 256 threads
    int tx = t & 15;                   // 16 cols of 4
    int ty = t >> 4;                   // 16 row-groups of (4 + 4 split)

    // ---- global load indices (float4 along K) ----
    int arow0 = t >> 2;                // 0..63   (two iters: +64)
    int akq   = t & 3;                 // k-quarter
    int brow  = t >> 2;                // 0..63
    int bkq   = t & 3;

    float4 pa0, pa1, pb;
    auto load_tile = [&](int k0) {
        pa0 = *(const float4*)(A + (size_t)(bm + arow0) * K + k0 + akq * 4);
        pa1 = *(const float4*)(A + (size_t)(bm + arow0 + 64) * K + k0 + akq * 4);
        if (mode == 1) {
            float4 r0 = *(const float4*)(Aadd + (size_t)(bm + arow0) * K + k0 + akq * 4);
            float4 r1 = *(const float4*)(Aadd + (size_t)(bm + arow0 + 64) * K + k0 + akq * 4);
            pa0.x += r0.x; pa0.y += r0.y; pa0.z += r0.z; pa0.w += r0.w;
            pa1.x += r1.x; pa1.y += r1.y; pa1.z += r1.z; pa1.w += r1.w;
        }
        pb = *(const float4*)(Wm + (size_t)(bn + brow) * K + k0 + bkq * 4);
    };
    auto store_tile = [&](int buf) {
        sA[buf][akq * 4 + 0][arow0] = pa0.x;
        sA[buf][akq * 4 + 1][arow0] = pa0.y;
        sA[buf][akq * 4 + 2][arow0] = pa0.z;
        sA[buf][akq * 4 + 3][arow0] = pa0.w;
        sA[buf][akq * 4 + 0][arow0 + 64] = pa1.x;
        sA[buf][akq * 4 + 1][arow0 + 64] = pa1.y;
        sA[buf][akq * 4 + 2][arow0 + 64] = pa1.z;
        sA[buf][akq * 4 + 3][arow0 + 64] = pa1.w;
        sB[buf][bkq * 4 + 0][brow] = pb.x;
        sB[buf][bkq * 4 + 1][brow] = pb.y;
        sB[buf][bkq * 4 + 2][brow] = pb.z;
        sB[buf][bkq * 4 + 3][brow] = pb.w;
    };

    float acc[8][4];
    #pragma unroll
    for (int i = 0; i < 8; i++)
        #pragma unroll
        for (int j = 0; j < 4; j++) acc[i][j] = 0.f;

    load_tile(0);
    store_tile(0);
    __syncthreads();

    const int NT = K / GBK;            // 16
    #pragma unroll 1
    for (int kt = 0; kt < NT; kt++) {
        int buf = kt & 1;
        if (kt + 1 < NT) load_tile((kt + 1) * GBK);

        #pragma unroll
        for (int k = 0; k < GBK; k++) {
            float ra[8], rb[4];
            #pragma unroll
            for (int i = 0; i < 4; i++) ra[i]     = sA[buf][k][ty * 4 + i];
            #pragma unroll
            for (int i = 0; i < 4; i++) ra[4 + i] = sA[buf][k][64 + ty * 4 + i];
            #pragma unroll
            for (int j = 0; j < 4; j++) rb[j]     = sB[buf][k][tx * 4 + j];
            #pragma unroll
            for (int i = 0; i < 8; i++)
                #pragma unroll
                for (int j = 0; j < 4; j++)
                    acc[i][j] = fmaf(ra[i], rb[j], acc[i][j]);
        }

        if (kt + 1 < NT) {
            store_tile(1 - buf);
            __syncthreads();
        }
    }

    // ---- epilogue: bias + float4 stores ----
    float4 bv = *(const float4*)(bias + bn + tx * 4);
    #pragma unroll
    for (int i = 0; i < 8; i++) {
        int row = (i < 4) ? (ty * 4 + i) : (64 + ty * 4 + (i - 4));
        float4 o;
        o.x = acc[i][0] + bv.x;
        o.y = acc[i][1] + bv.y;
        o.z = acc[i][2] + bv.z;
        o.w = acc[i][3] + bv.w;
        *(float4*)(C + (size_t)(bm + row) * 256 + bn + tx * 4) = o;
    }
}

// ---------------- launch ----------------
extern "C" void kernel_launch(void* const* d_in, const int* in_sizes, int n_in,
                              void* d_out, int out_size) {
    const float* instf  = (const float*)d_in[0];
    const float* anchor = (const float*)d_in[1];
    const float* proj   = (const float*)d_in[2];
    const float* f0     = (const float*)d_in[3];
    const float* f1     = (const float*)d_in[4];
    const float* f2     = (const float*)d_in[5];
    const float* f3     = (const float*)d_in[6];
    const float* attn_w = (const float*)d_in[7];
    const float* attn_b = (const float*)d_in[8];
    const float* vp_w   = (const float*)d_in[9];
    const float* vp_b   = (const float*)d_in[10];
    const float* op_w   = (const float*)d_in[11];
    const float* op_b   = (const float*)d_in[12];
    float* out = (float*)d_out;

    // 1) transpose features to channel-last (exact grid per level)
    dim3 tb(32, 8);
    transpose_kernel<0><<<dim3(352, 8, B * CAMS), tb>>>(f0);   // 64x176
    transpose_kernel<1><<<dim3(88,  8, B * CAMS), tb>>>(f1);   // 32x88
    transpose_kernel<2><<<dim3(22,  8, B * CAMS), tb>>>(f2);   // 16x44
    transpose_kernel<3><<<dim3(6,   8, B * CAMS), tb>>>(f3);   // 8x22

    // 2) attn softmax + uv
    prep_kernel<<<(BN_PTS * 32 + 255) / 256, 256>>>(instf, anchor, proj, attn_w, attn_b);

    // 3) aggregate (4 points / block)
    aggregate_kernel<<<BN_PTS / 4, 256>>>();

    // 4) GEMMs
    dim3 gg(BN_PTS / GBM, 256 / GBN);
    gemm_nt_kernel<<<gg, 256>>>(0, vp_w, vp_b, nullptr, out);
    gemm_nt_kernel<<<gg, 256>>>(1, op_w, op_b, instf, out);
}